// round 13
// baseline (speedup 1.0000x reference)
#include <cuda_runtime.h>
#include <math.h>

#define EMB    4096
#define DIM    4096
#define TPREV  8192
#define TTOT   (TPREV + 1)     // 8193
#define NCHUNK 64
#define CHUNK  (EMB / NCHUNK)  // 64
#define TPAD   8224            // padded stride for partials (mult of 32)

// Scratch (device globals — no allocation allowed)
__device__ __align__(16) float g_q[DIM];
__device__ __align__(16) float g_k[DIM];
__device__ __align__(16) float g_v[DIM];
__device__ __align__(16) float g_part[NCHUNK * TPAD];
__device__ __align__(16) float g_a[TTOT + 3];

__device__ __forceinline__ float warp_red(float v) {
#pragma unroll
    for (int off = 16; off; off >>= 1)
        v += __shfl_xor_sync(0xffffffffu, v, off);
    return v;
}

// R11-proven GEMV body: 4 batches of (8 streaming W + 8 L1 x) LDG.128.
__device__ __forceinline__ float gemv_row(const float4* __restrict__ wr,
                                          const float4* __restrict__ xv,
                                          int lane) {
    float acc = 0.0f;
#pragma unroll
    for (int b = 0; b < 4; b++) {
        float4 w[8], xx[8];
#pragma unroll
        for (int j = 0; j < 8; j++)          // DRAM loads front-batched
            w[j] = __ldcs(&wr[lane + (b * 8 + j) * 32]);
#pragma unroll
        for (int j = 0; j < 8; j++)          // L1-resident loads after
            xx[j] = __ldg(&xv[lane + (b * 8 + j) * 32]);
#pragma unroll
        for (int j = 0; j < 8; j++)
            acc += w[j].x * xx[j].x + w[j].y * xx[j].y
                 + w[j].z * xx[j].z + w[j].w * xx[j].w;
    }
    return warp_red(acc);
}

// ---------------------------------------------------------------------------
// Kernel 1: q,k = W{q,k} @ x only (score's true dependency).
// 8192 warps -> 1024 blocks of 256.
// ---------------------------------------------------------------------------
__global__ void __launch_bounds__(256, 4)
qk_kernel(const float* __restrict__ x,
          const float* __restrict__ Wq,
          const float* __restrict__ Wk) {
    int gw   = (blockIdx.x * blockDim.x + threadIdx.x) >> 5;
    int lane = threadIdx.x & 31;
    int which = gw >> 12;                    // 0 = q, 1 = k
    int row   = gw & (DIM - 1);

    const float* W = (which == 0) ? Wq : Wk;
    const float4* wr = reinterpret_cast<const float4*>(W) + (size_t)row * (EMB / 4);
    const float4* xv = reinterpret_cast<const float4*>(x);

    float acc = gemv_row(wr, xv, lane);
    if (lane == 0)
        ((which == 0) ? g_q : g_k)[row] = acc;
}

// ---------------------------------------------------------------------------
// Kernel 2: FUSED score partials (blocks 0..511) + v-projection (512..1023).
// Score: chunk c = bx>>3, t4 = (bx&7)*256+tid; unroll-16 streaming loads.
// Vproj: R11 GEMV body on Wv rows. Both stream DRAM -> overlap in one kernel.
// ---------------------------------------------------------------------------
__global__ void __launch_bounds__(256, 4)
score_vproj_kernel(const float* __restrict__ Kc,
                   const float* __restrict__ x,
                   const float* __restrict__ Wv) {
    if (blockIdx.x < 512) {
        __shared__ float sq[CHUNK];
        int c  = blockIdx.x >> 3;
        int d0 = c * CHUNK;
        if (threadIdx.x < CHUNK)
            sq[threadIdx.x] = g_q[d0 + threadIdx.x];
        __syncthreads();

        int t4 = (blockIdx.x & 7) * 256 + threadIdx.x;    // 0..2047
        const float4* col = reinterpret_cast<const float4*>(Kc) +
                            (size_t)d0 * (TPREV / 4) + t4;

        float4 acc = make_float4(0.f, 0.f, 0.f, 0.f);
#pragma unroll 16
        for (int d = 0; d < CHUNK; d++) {
            float4 kk = __ldcs(&col[(size_t)d * (TPREV / 4)]);
            float  s  = sq[d];
            acc.x += s * kk.x; acc.y += s * kk.y;
            acc.z += s * kk.z; acc.w += s * kk.w;
        }
        reinterpret_cast<float4*>(g_part + c * TPAD)[t4] = acc;
    } else {
        int warp = threadIdx.x >> 5;
        int lane = threadIdx.x & 31;
        int row  = (blockIdx.x - 512) * 8 + warp;         // 0..4095

        const float4* wr = reinterpret_cast<const float4*>(Wv) + (size_t)row * (EMB / 4);
        const float4* xv = reinterpret_cast<const float4*>(x);

        float acc = gemv_row(wr, xv, lane);
        if (lane == 0)
            g_v[row] = acc;
    }
}

// ---------------------------------------------------------------------------
// Kernel 3: reduce partials -> sigmoid scores. 33 blocks of 256:
// blocks 0..31 reduce over 64 chunks; block 32 computes the t=8192 tail.
// ---------------------------------------------------------------------------
__global__ void sigmoid_kernel() {
    if (blockIdx.x < 32) {
        int t = blockIdx.x * 256 + threadIdx.x;
        float s = 0.0f;
#pragma unroll
        for (int c = 0; c < NCHUNK; c++)
            s += g_part[c * TPAD + t];
        s *= 0.015625f;  // 1/sqrt(4096)
        g_a[t] = 1.0f / (1.0f + expf(-s));
    } else {
        __shared__ float red[256];
        float s = 0.0f;
#pragma unroll
        for (int j = 0; j < 16; j++) {
            int d = threadIdx.x + 256 * j;
            s += g_q[d] * g_k[d];
        }
        red[threadIdx.x] = s;
        __syncthreads();
#pragma unroll
        for (int w = 128; w >= 1; w >>= 1) {
            if (threadIdx.x < w) red[threadIdx.x] += red[threadIdx.x + w];
            __syncthreads();
        }
        if (threadIdx.x == 0) {
            float v = red[0] * 0.015625f;
            g_a[TPREV] = 1.0f / (1.0f + expf(-v));
        }
    }
}

// ---------------------------------------------------------------------------
// Kernel 4: z[d] = V_cache[d,:] . a[0:T] + v[d]*a[T].  (R11 proven body)
// ONE warp per row; 8 batches of (8 streaming V + 8 L1 a) LDG.128.
// 4096 warps -> 512 blocks of 256.
// ---------------------------------------------------------------------------
__global__ void __launch_bounds__(256, 4)
out_kernel(const float* __restrict__ Vc, float* __restrict__ out) {
    int warp = threadIdx.x >> 5;
    int lane = threadIdx.x & 31;
    int row  = blockIdx.x * 8 + warp;

    const float4* vr = reinterpret_cast<const float4*>(Vc) + (size_t)row * (TPREV / 4);
    const float4* av = reinterpret_cast<const float4*>(g_a);

    float acc = 0.0f;
#pragma unroll
    for (int b = 0; b < 8; b++) {
        float4 v[8], a[8];
#pragma unroll
        for (int j = 0; j < 8; j++)
            v[j] = __ldcs(&vr[lane + (b * 8 + j) * 32]);
#pragma unroll
        for (int j = 0; j < 8; j++)
            a[j] = __ldg(&av[lane + (b * 8 + j) * 32]);
#pragma unroll
        for (int j = 0; j < 8; j++)
            acc += v[j].x * a[j].x + v[j].y * a[j].y
                 + v[j].z * a[j].z + v[j].w * a[j].w;
    }
    acc = warp_red(acc);

    if (lane == 0)
        out[row] = acc + g_v[row] * g_a[TPREV];
}

// ---------------------------------------------------------------------------
extern "C" void kernel_launch(void* const* d_in, const int* in_sizes, int n_in,
                              void* d_out, int out_size) {
    const float* x  = (const float*)d_in[0];
    const float* Wq = (const float*)d_in[1];
    const float* Wk = (const float*)d_in[2];
    const float* Wv = (const float*)d_in[3];
    const float* Kc = (const float*)d_in[4];
    const float* Vc = (const float*)d_in[5];
    float* out = (float*)d_out;

    qk_kernel<<<(2 * DIM) / 8, 256>>>(x, Wq, Wk);

    score_vproj_kernel<<<1088, 256>>>(Kc, x, Wv);

    sigmoid_kernel<<<33, 256>>>();

    out_kernel<<<DIM / 8, 256>>>(Vc, out);
}

// round 14
// speedup vs baseline: 1.0544x; 1.0544x over previous
#include <cuda_runtime.h>
#include <math.h>

#define EMB    4096
#define DIM    4096
#define TPREV  8192
#define TTOT   (TPREV + 1)     // 8193
#define NCHUNK 64
#define CHUNK  (EMB / NCHUNK)  // 64
#define TPAD   8224            // padded stride for partials (mult of 32)

// Scratch (device globals — no allocation allowed)
__device__ __align__(16) float g_q[DIM];
__device__ __align__(16) float g_k[DIM];
__device__ __align__(16) float g_v[DIM];
__device__ __align__(16) float g_part[NCHUNK * TPAD];
__device__ __align__(16) float g_a[TTOT + 3];

__device__ __forceinline__ float warp_red(float v) {
#pragma unroll
    for (int off = 16; off; off >>= 1)
        v += __shfl_xor_sync(0xffffffffu, v, off);
    return v;
}

// ---------------------------------------------------------------------------
// Kernel 1: q/k/v = W{q,k,v} @ x — ONE warp per output row. x staged in smem;
// 2 batches of 16 streaming W loads (__ldcs) held in regs; x from LDS pipe.
// 12288 warps -> 1536 blocks of 256. Reg budget 85 (launch_bounds 256,3).
// ---------------------------------------------------------------------------
__global__ void __launch_bounds__(256, 3)
qkv_kernel(const float* __restrict__ x,
           const float* __restrict__ Wq,
           const float* __restrict__ Wk,
           const float* __restrict__ Wv) {
    __shared__ float4 sx[EMB / 4];            // 16 KB
    const float4* xv = reinterpret_cast<const float4*>(x);
#pragma unroll
    for (int i = 0; i < 4; i++)
        sx[threadIdx.x + i * 256] = __ldg(&xv[threadIdx.x + i * 256]);
    __syncthreads();

    int gw   = (blockIdx.x * blockDim.x + threadIdx.x) >> 5;
    int lane = threadIdx.x & 31;
    int which = gw >> 12;
    int row   = gw & (DIM - 1);

    const float* W = (which == 0) ? Wq : (which == 1) ? Wk : Wv;
    const float4* wr = reinterpret_cast<const float4*>(W) + (size_t)row * (EMB / 4);

    float acc0 = 0.0f, acc1 = 0.0f;
#pragma unroll
    for (int b = 0; b < 2; b++) {             // 2 batches of 16 float4 per lane
        float4 w[16];
#pragma unroll
        for (int j = 0; j < 16; j++)          // 16 DRAM loads front-batched
            w[j] = __ldcs(&wr[lane + (b * 16 + j) * 32]);
#pragma unroll
        for (int j = 0; j < 16; j++) {        // x from smem (LDS pipe)
            float4 xx = sx[lane + (b * 16 + j) * 32];
            if (j & 1)
                acc1 += w[j].x * xx.x + w[j].y * xx.y + w[j].z * xx.z + w[j].w * xx.w;
            else
                acc0 += w[j].x * xx.x + w[j].y * xx.y + w[j].z * xx.z + w[j].w * xx.w;
        }
    }
    float acc = warp_red(acc0 + acc1);

    if (lane == 0) {
        float* dst = (which == 0) ? g_q : (which == 1) ? g_k : g_v;
        dst[row] = acc;
    }
}

// ---------------------------------------------------------------------------
// Kernel 2: partial scores (R11 proven). Grid (8, 64), block 256 -> 4096 warps.
// Thread owns one float4 along t, chunk of 64 d; unroll 16 front-batches
// independent streaming LDG.128. Deterministic partials. Tail in kernel 3.
// ---------------------------------------------------------------------------
__global__ void __launch_bounds__(256, 4)
score_partial_kernel(const float* __restrict__ Kc) {
    __shared__ float sq[CHUNK];
    int c  = blockIdx.y;
    int d0 = c * CHUNK;
    if (threadIdx.x < CHUNK)
        sq[threadIdx.x] = g_q[d0 + threadIdx.x];
    __syncthreads();

    int t4 = blockIdx.x * blockDim.x + threadIdx.x;   // 0..2047
    const float4* col = reinterpret_cast<const float4*>(Kc) +
                        (size_t)d0 * (TPREV / 4) + t4;

    float4 acc = make_float4(0.f, 0.f, 0.f, 0.f);
#pragma unroll 16
    for (int d = 0; d < CHUNK; d++) {
        float4 kk = __ldcs(&col[(size_t)d * (TPREV / 4)]);
        float  s  = sq[d];
        acc.x += s * kk.x; acc.y += s * kk.y;
        acc.z += s * kk.z; acc.w += s * kk.w;
    }
    reinterpret_cast<float4*>(g_part + c * TPAD)[t4] = acc;
}

// ---------------------------------------------------------------------------
// Kernel 3: reduce partials -> sigmoid scores. 33 blocks of 256:
// blocks 0..31 reduce over 64 chunks; block 32 computes the t=8192 tail.
// ---------------------------------------------------------------------------
__global__ void sigmoid_kernel() {
    if (blockIdx.x < 32) {
        int t = blockIdx.x * 256 + threadIdx.x;
        float s = 0.0f;
#pragma unroll
        for (int c = 0; c < NCHUNK; c++)
            s += g_part[c * TPAD + t];
        s *= 0.015625f;  // 1/sqrt(4096)
        g_a[t] = 1.0f / (1.0f + expf(-s));
    } else {
        __shared__ float red[256];
        float s = 0.0f;
#pragma unroll
        for (int j = 0; j < 16; j++) {
            int d = threadIdx.x + 256 * j;
            s += g_q[d] * g_k[d];
        }
        red[threadIdx.x] = s;
        __syncthreads();
#pragma unroll
        for (int w = 128; w >= 1; w >>= 1) {
            if (threadIdx.x < w) red[threadIdx.x] += red[threadIdx.x + w];
            __syncthreads();
        }
        if (threadIdx.x == 0) {
            float v = red[0] * 0.015625f;
            g_a[TPREV] = 1.0f / (1.0f + expf(-v));
        }
    }
}

// ---------------------------------------------------------------------------
// Kernel 4: z[d] = V_cache[d,:] . a[0:T] + v[d]*a[T].
// ONE warp per row. a staged in smem (32KB, LDS pipe); 4 batches of 16
// streaming V loads (__ldcs) held in regs -> 16 outstanding DRAM loads/thread
// (score's shape). 4096 warps -> 512 blocks of 256. Reg budget 85.
// ---------------------------------------------------------------------------
__global__ void __launch_bounds__(256, 3)
out_kernel(const float* __restrict__ Vc, float* __restrict__ out) {
    __shared__ float4 sa[TPREV / 4];          // 32 KB
    const float4* av = reinterpret_cast<const float4*>(g_a);
#pragma unroll
    for (int i = 0; i < 8; i++)
        sa[threadIdx.x + i * 256] = __ldg(&av[threadIdx.x + i * 256]);
    __syncthreads();

    int warp = threadIdx.x >> 5;
    int lane = threadIdx.x & 31;
    int row  = blockIdx.x * 8 + warp;

    const float4* vr = reinterpret_cast<const float4*>(Vc) + (size_t)row * (TPREV / 4);

    float acc0 = 0.0f, acc1 = 0.0f;
#pragma unroll
    for (int b = 0; b < 4; b++) {             // 4 batches of 16 float4 per lane
        float4 v[16];
#pragma unroll
        for (int j = 0; j < 16; j++)          // 16 DRAM loads front-batched
            v[j] = __ldcs(&vr[lane + (b * 16 + j) * 32]);
#pragma unroll
        for (int j = 0; j < 16; j++) {        // a from smem (LDS pipe)
            float4 a = sa[lane + (b * 16 + j) * 32];
            if (j & 1)
                acc1 += v[j].x * a.x + v[j].y * a.y + v[j].z * a.z + v[j].w * a.w;
            else
                acc0 += v[j].x * a.x + v[j].y * a.y + v[j].z * a.z + v[j].w * a.w;
        }
    }
    float acc = warp_red(acc0 + acc1);

    if (lane == 0)
        out[row] = acc + g_v[row] * g_a[TPREV];
}

// ---------------------------------------------------------------------------
extern "C" void kernel_launch(void* const* d_in, const int* in_sizes, int n_in,
                              void* d_out, int out_size) {
    const float* x  = (const float*)d_in[0];
    const float* Wq = (const float*)d_in[1];
    const float* Wk = (const float*)d_in[2];
    const float* Wv = (const float*)d_in[3];
    const float* Kc = (const float*)d_in[4];
    const float* Vc = (const float*)d_in[5];
    float* out = (float*)d_out;

    qkv_kernel<<<(3 * DIM) / 8, 256>>>(x, Wq, Wk, Wv);

    dim3 sg(TPREV / (256 * 4), NCHUNK);          // (8, 64)
    score_partial_kernel<<<sg, 256>>>(Kc);

    sigmoid_kernel<<<33, 256>>>();

    out_kernel<<<DIM / 8, 256>>>(Vc, out);
}

// round 15
// speedup vs baseline: 1.0964x; 1.0399x over previous
#include <cuda_runtime.h>
#include <math.h>

#define EMB    4096
#define DIM    4096
#define TPREV  8192
#define TTOT   (TPREV + 1)     // 8193
#define NCHUNK 64
#define CHUNK  (EMB / NCHUNK)  // 64
#define TPAD   8224            // padded stride for partials (mult of 32)

// Scratch (device globals — no allocation allowed)
__device__ __align__(16) float g_q[DIM];
__device__ __align__(16) float g_k[DIM];
__device__ __align__(16) float g_v[DIM];
__device__ __align__(16) float g_part[NCHUNK * TPAD];
__device__ __align__(16) float g_a[TTOT + 3];
__device__ __align__(16) float g_opart[2 * DIM];

__device__ __forceinline__ float warp_red(float v) {
#pragma unroll
    for (int off = 16; off; off >>= 1)
        v += __shfl_xor_sync(0xffffffffu, v, off);
    return v;
}

// ---------------------------------------------------------------------------
// Kernel 1: q/k/v = W{q,k,v} @ x — ONE warp per output row (R11 proven body).
// 4 batches of (8 streaming W + 8 L1 x) LDG.128. 12288 warps -> 1536 blocks.
// ---------------------------------------------------------------------------
__global__ void __launch_bounds__(256, 4)
qkv_kernel(const float* __restrict__ x,
           const float* __restrict__ Wq,
           const float* __restrict__ Wk,
           const float* __restrict__ Wv) {
    int gw   = (blockIdx.x * blockDim.x + threadIdx.x) >> 5;
    int lane = threadIdx.x & 31;
    int which = gw >> 12;
    int row   = gw & (DIM - 1);

    const float* W = (which == 0) ? Wq : (which == 1) ? Wk : Wv;
    const float4* wr = reinterpret_cast<const float4*>(W) + (size_t)row * (EMB / 4);
    const float4* xv = reinterpret_cast<const float4*>(x);

    float acc = 0.0f;
#pragma unroll
    for (int b = 0; b < 4; b++) {
        float4 w[8], xx[8];
#pragma unroll
        for (int j = 0; j < 8; j++)
            w[j] = __ldcs(&wr[lane + (b * 8 + j) * 32]);
#pragma unroll
        for (int j = 0; j < 8; j++)
            xx[j] = __ldg(&xv[lane + (b * 8 + j) * 32]);
#pragma unroll
        for (int j = 0; j < 8; j++)
            acc += w[j].x * xx[j].x + w[j].y * xx[j].y
                 + w[j].z * xx[j].z + w[j].w * xx[j].w;
    }
    acc = warp_red(acc);

    if (lane == 0) {
        float* dst = (which == 0) ? g_q : (which == 1) ? g_k : g_v;
        dst[row] = acc;
    }
}

// ---------------------------------------------------------------------------
// Kernel 2: partial scores (R11 proven). Grid (8, 64), block 256.
// ---------------------------------------------------------------------------
__global__ void __launch_bounds__(256, 4)
score_partial_kernel(const float* __restrict__ Kc) {
    __shared__ float sq[CHUNK];
    int c  = blockIdx.y;
    int d0 = c * CHUNK;
    if (threadIdx.x < CHUNK)
        sq[threadIdx.x] = g_q[d0 + threadIdx.x];
    __syncthreads();

    int t4 = blockIdx.x * blockDim.x + threadIdx.x;   // 0..2047
    const float4* col = reinterpret_cast<const float4*>(Kc) +
                        (size_t)d0 * (TPREV / 4) + t4;

    float4 acc = make_float4(0.f, 0.f, 0.f, 0.f);
#pragma unroll 16
    for (int d = 0; d < CHUNK; d++) {
        float4 kk = __ldcs(&col[(size_t)d * (TPREV / 4)]);
        float  s  = sq[d];
        acc.x += s * kk.x; acc.y += s * kk.y;
        acc.z += s * kk.z; acc.w += s * kk.w;
    }
    reinterpret_cast<float4*>(g_part + c * TPAD)[t4] = acc;
}

// ---------------------------------------------------------------------------
// Kernel 3: reduce partials -> sigmoid scores. 33 blocks of 256.
// ---------------------------------------------------------------------------
__global__ void sigmoid_kernel() {
    if (blockIdx.x < 32) {
        int t = blockIdx.x * 256 + threadIdx.x;
        float s = 0.0f;
#pragma unroll
        for (int c = 0; c < NCHUNK; c++)
            s += g_part[c * TPAD + t];
        s *= 0.015625f;  // 1/sqrt(4096)
        g_a[t] = 1.0f / (1.0f + expf(-s));
    } else {
        __shared__ float red[256];
        float s = 0.0f;
#pragma unroll
        for (int j = 0; j < 16; j++) {
            int d = threadIdx.x + 256 * j;
            s += g_q[d] * g_k[d];
        }
        red[threadIdx.x] = s;
        __syncthreads();
#pragma unroll
        for (int w = 128; w >= 1; w >>= 1) {
            if (threadIdx.x < w) red[threadIdx.x] += red[threadIdx.x + w];
            __syncthreads();
        }
        if (threadIdx.x == 0) {
            float v = red[0] * 0.015625f;
            g_a[TPREV] = 1.0f / (1.0f + expf(-v));
        }
    }
}

// ---------------------------------------------------------------------------
// Kernel 4: out partials. TWO warps per row, each a half t-range, NO smem
// combine (gmem partial, single writer -> deterministic). Body identical to
// qkv: 4 batches of (8 streaming V + 8 L1 a). 8192 warps -> 1024 blocks.
// ---------------------------------------------------------------------------
__global__ void __launch_bounds__(256, 4)
out_part_kernel(const float* __restrict__ Vc) {
    int gw   = (blockIdx.x * blockDim.x + threadIdx.x) >> 5;  // 0..8191
    int lane = threadIdx.x & 31;
    int half = gw >> 12;
    int row  = gw & (DIM - 1);

    const float4* vr = reinterpret_cast<const float4*>(Vc) + (size_t)row * (TPREV / 4)
                       + half * (TPREV / 8);
    const float4* av = reinterpret_cast<const float4*>(g_a) + half * (TPREV / 8);

    float acc = 0.0f;
#pragma unroll
    for (int b = 0; b < 4; b++) {
        float4 v[8], a[8];
#pragma unroll
        for (int j = 0; j < 8; j++)
            v[j] = __ldcs(&vr[lane + (b * 8 + j) * 32]);
#pragma unroll
        for (int j = 0; j < 8; j++)
            a[j] = __ldg(&av[lane + (b * 8 + j) * 32]);
#pragma unroll
        for (int j = 0; j < 8; j++)
            acc += v[j].x * a[j].x + v[j].y * a[j].y
                 + v[j].z * a[j].z + v[j].w * a[j].w;
    }
    acc = warp_red(acc);

    if (lane == 0)
        g_opart[half * DIM + row] = acc;
}

// ---------------------------------------------------------------------------
// Kernel 5: finish — fold the two half partials + current-step v*a tail.
// ---------------------------------------------------------------------------
__global__ void finish_kernel(float* __restrict__ out) {
    int i = blockIdx.x * blockDim.x + threadIdx.x;
    out[i] = g_opart[i] + g_opart[DIM + i] + g_v[i] * g_a[TPREV];
}

// ---------------------------------------------------------------------------
extern "C" void kernel_launch(void* const* d_in, const int* in_sizes, int n_in,
                              void* d_out, int out_size) {
    const float* x  = (const float*)d_in[0];
    const float* Wq = (const float*)d_in[1];
    const float* Wk = (const float*)d_in[2];
    const float* Wv = (const float*)d_in[3];
    const float* Kc = (const float*)d_in[4];
    const float* Vc = (const float*)d_in[5];
    float* out = (float*)d_out;

    qkv_kernel<<<(3 * DIM) / 8, 256>>>(x, Wq, Wk, Wv);

    dim3 sg(TPREV / (256 * 4), NCHUNK);          // (8, 64)
    score_partial_kernel<<<sg, 256>>>(Kc);

    sigmoid_kernel<<<33, 256>>>();

    out_part_kernel<<<(2 * DIM) / 8, 256>>>(Vc);

    finish_kernel<<<DIM / 256, 256>>>(out);
}

// round 16
// speedup vs baseline: 1.1054x; 1.0082x over previous
#include <cuda_runtime.h>
#include <math.h>

#define EMB    4096
#define DIM    4096
#define TPREV  8192
#define TTOT   (TPREV + 1)     // 8193
#define NCHUNK 64
#define CHUNK  (EMB / NCHUNK)  // 64
#define TPAD   8224            // padded stride for partials (mult of 32)

// Scratch (device globals — no allocation allowed)
__device__ __align__(16) float g_q[DIM];
__device__ __align__(16) float g_k[DIM];
__device__ __align__(16) float g_v[DIM];
__device__ __align__(16) float g_part[NCHUNK * TPAD];
__device__ __align__(16) float g_a[TTOT + 3];

__device__ __forceinline__ float warp_red(float v) {
#pragma unroll
    for (int off = 16; off; off >>= 1)
        v += __shfl_xor_sync(0xffffffffu, v, off);
    return v;
}

// ---------------------------------------------------------------------------
// Kernel 1: q/k/v = W{q,k,v} @ x — ONE warp per output row, SOFTWARE-PIPELINED:
// double-buffered 8-deep DRAM batches (w0/w1 ping-pong); batch b+1's loads
// issue before batch b's consume, so the DRAM queue never drains.
// x consumed per-FMA from L1. 12288 warps -> 1536 blocks of 256.
// ---------------------------------------------------------------------------
__global__ void __launch_bounds__(256, 3)
qkv_kernel(const float* __restrict__ x,
           const float* __restrict__ Wq,
           const float* __restrict__ Wk,
           const float* __restrict__ Wv) {
    int gw   = (blockIdx.x * blockDim.x + threadIdx.x) >> 5;
    int lane = threadIdx.x & 31;
    int which = gw >> 12;
    int row   = gw & (DIM - 1);

    const float* W = (which == 0) ? Wq : (which == 1) ? Wk : Wv;
    const float4* wr = reinterpret_cast<const float4*>(W) + (size_t)row * (EMB / 4);
    const float4* xv = reinterpret_cast<const float4*>(x);

    float4 w0[8], w1[8];
#pragma unroll
    for (int j = 0; j < 8; j++)              // prologue: batch 0 in flight
        w0[j] = __ldcs(&wr[lane + j * 32]);

    float acc = 0.0f;
#pragma unroll
    for (int b = 0; b < 4; b++) {            // 4 batches of 8 float4 per lane
        float4* cur = (b & 1) ? w1 : w0;
        float4* nxt = (b & 1) ? w0 : w1;
        if (b < 3) {
#pragma unroll
            for (int j = 0; j < 8; j++)      // prefetch next batch FIRST
                nxt[j] = __ldcs(&wr[lane + ((b + 1) * 8 + j) * 32]);
        }
#pragma unroll
        for (int j = 0; j < 8; j++) {        // consume current batch
            float4 xx = __ldg(&xv[lane + (b * 8 + j) * 32]);
            acc += cur[j].x * xx.x + cur[j].y * xx.y
                 + cur[j].z * xx.z + cur[j].w * xx.w;
        }
    }
    acc = warp_red(acc);

    if (lane == 0) {
        float* dst = (which == 0) ? g_q : (which == 1) ? g_k : g_v;
        dst[row] = acc;
    }
}

// ---------------------------------------------------------------------------
// Kernel 2: partial scores (R11 proven). Grid (8, 64), block 256.
// ---------------------------------------------------------------------------
__global__ void __launch_bounds__(256, 4)
score_partial_kernel(const float* __restrict__ Kc) {
    __shared__ float sq[CHUNK];
    int c  = blockIdx.y;
    int d0 = c * CHUNK;
    if (threadIdx.x < CHUNK)
        sq[threadIdx.x] = g_q[d0 + threadIdx.x];
    __syncthreads();

    int t4 = blockIdx.x * blockDim.x + threadIdx.x;   // 0..2047
    const float4* col = reinterpret_cast<const float4*>(Kc) +
                        (size_t)d0 * (TPREV / 4) + t4;

    float4 acc = make_float4(0.f, 0.f, 0.f, 0.f);
#pragma unroll 16
    for (int d = 0; d < CHUNK; d++) {
        float4 kk = __ldcs(&col[(size_t)d * (TPREV / 4)]);
        float  s  = sq[d];
        acc.x += s * kk.x; acc.y += s * kk.y;
        acc.z += s * kk.z; acc.w += s * kk.w;
    }
    reinterpret_cast<float4*>(g_part + c * TPAD)[t4] = acc;
}

// ---------------------------------------------------------------------------
// Kernel 3: reduce partials -> sigmoid scores. 33 blocks of 256.
// ---------------------------------------------------------------------------
__global__ void sigmoid_kernel() {
    if (blockIdx.x < 32) {
        int t = blockIdx.x * 256 + threadIdx.x;
        float s = 0.0f;
#pragma unroll
        for (int c = 0; c < NCHUNK; c++)
            s += g_part[c * TPAD + t];
        s *= 0.015625f;  // 1/sqrt(4096)
        g_a[t] = 1.0f / (1.0f + expf(-s));
    } else {
        __shared__ float red[256];
        float s = 0.0f;
#pragma unroll
        for (int j = 0; j < 16; j++) {
            int d = threadIdx.x + 256 * j;
            s += g_q[d] * g_k[d];
        }
        red[threadIdx.x] = s;
        __syncthreads();
#pragma unroll
        for (int w = 128; w >= 1; w >>= 1) {
            if (threadIdx.x < w) red[threadIdx.x] += red[threadIdx.x + w];
            __syncthreads();
        }
        if (threadIdx.x == 0) {
            float v = red[0] * 0.015625f;
            g_a[TPREV] = 1.0f / (1.0f + expf(-v));
        }
    }
}

// ---------------------------------------------------------------------------
// Kernel 4: z[d] = V_cache[d,:] . a[0:T] + v[d]*a[T].
// ONE warp per row, SOFTWARE-PIPELINED: double-buffered 8-deep DRAM batches
// (v0/v1 ping-pong); next batch issues before current consume; a per-FMA
// from L1. 4096 warps -> 512 blocks of 256.
// ---------------------------------------------------------------------------
__global__ void __launch_bounds__(256, 3)
out_kernel(const float* __restrict__ Vc, float* __restrict__ out) {
    int warp = threadIdx.x >> 5;
    int lane = threadIdx.x & 31;
    int row  = blockIdx.x * 8 + warp;

    const float4* vr = reinterpret_cast<const float4*>(Vc) + (size_t)row * (TPREV / 4);
    const float4* av = reinterpret_cast<const float4*>(g_a);

    float4 v0[8], v1[8];
#pragma unroll
    for (int j = 0; j < 8; j++)              // prologue: batch 0 in flight
        v0[j] = __ldcs(&vr[lane + j * 32]);

    float acc = 0.0f;
#pragma unroll
    for (int b = 0; b < 8; b++) {            // 8 batches of 8 float4 per lane
        float4* cur = (b & 1) ? v1 : v0;
        float4* nxt = (b & 1) ? v0 : v1;
        if (b < 7) {
#pragma unroll
            for (int j = 0; j < 8; j++)      // prefetch next batch FIRST
                nxt[j] = __ldcs(&vr[lane + ((b + 1) * 8 + j) * 32]);
        }
#pragma unroll
        for (int j = 0; j < 8; j++) {        // consume current batch
            float4 a = __ldg(&av[lane + (b * 8 + j) * 32]);
            acc += cur[j].x * a.x + cur[j].y * a.y
                 + cur[j].z * a.z + cur[j].w * a.w;
        }
    }
    acc = warp_red(acc);

    if (lane == 0)
        out[row] = acc + g_v[row] * g_a[TPREV];
}

// ---------------------------------------------------------------------------
extern "C" void kernel_launch(void* const* d_in, const int* in_sizes, int n_in,
                              void* d_out, int out_size) {
    const float* x  = (const float*)d_in[0];
    const float* Wq = (const float*)d_in[1];
    const float* Wk = (const float*)d_in[2];
    const float* Wv = (const float*)d_in[3];
    const float* Kc = (const float*)d_in[4];
    const float* Vc = (const float*)d_in[5];
    float* out = (float*)d_out;

    qkv_kernel<<<(3 * DIM) / 8, 256>>>(x, Wq, Wk, Wv);

    dim3 sg(TPREV / (256 * 4), NCHUNK);          // (8, 64)
    score_partial_kernel<<<sg, 256>>>(Kc);

    sigmoid_kernel<<<33, 256>>>();

    out_kernel<<<DIM / 8, 256>>>(Vc, out);
}